// round 1
// baseline (speedup 1.0000x reference)
#include <cuda_runtime.h>
#include <cuda_bf16.h>

// Problem constants (fixed by the reference)
#define NN   100000
#define EE   1600000
#define F_IN 128
#define HID  64
#define OUTD 40

// Scratch (device globals — no allocation allowed)
__device__ float g_uA[NN * HID];
__device__ float g_accA[NN * HID];
__device__ float g_uB[NN * HID];
__device__ float g_accB[NN * HID];
__device__ int   g_deg[NN];
__device__ float g_dis[NN];

// ---------------------------------------------------------------------------
// Degree / normalization prep
// ---------------------------------------------------------------------------
__global__ void count_deg_kernel(const int* __restrict__ dst, int E, int* __restrict__ deg) {
    int e = blockIdx.x * blockDim.x + threadIdx.x;
    if (e < E) atomicAdd(&deg[dst[e]], 1);
}

__global__ void dis_kernel(const int* __restrict__ deg, float* __restrict__ dis, int n) {
    int v = blockIdx.x * blockDim.x + threadIdx.x;
    if (v < n) dis[v] = rsqrtf((float)(deg[v] + 1));  // +1 self-loop; always >= 1
}

// ---------------------------------------------------------------------------
// GEMM: out = [maybe relu(dis[row]*X)] @ W + b, optionally scaled by dis[row].
// Writes result to out0 and (if non-null) out1 (acc starts as self-loop term u).
// Block: 256 threads; 32 rows per block; warp handles 4 rows; lane handles
// cols {lane, lane+32}.
// ---------------------------------------------------------------------------
template<int K, int NOUT, bool RELU_IN, bool SCALE_OUT>
__global__ void gemm_kernel(const float* __restrict__ X,
                            const float* __restrict__ W,
                            const float* __restrict__ B,
                            const float* __restrict__ dis,
                            float* __restrict__ out0,
                            float* __restrict__ out1,
                            int n) {
    __shared__ float Ws[K * NOUT];
    __shared__ float Xs[32 * K];

    int t = threadIdx.x;
    int row0 = blockIdx.x * 32;

    // Load weight tile (resident in L2 across blocks)
    #pragma unroll 4
    for (int i = t; i < K * NOUT; i += 256) Ws[i] = W[i];

    // Load X tile, fusing previous layer's scale+ReLU into the read
    #pragma unroll 4
    for (int i = t; i < 32 * K; i += 256) {
        int r = i / K, k = i - r * K;
        int gr = row0 + r;
        float v = 0.f;
        if (gr < n) {
            v = X[(size_t)gr * K + k];
            if (RELU_IN) v = fmaxf(v, 0.f) * dis[gr];
        }
        Xs[i] = v;
    }
    __syncthreads();

    int warp = t >> 5, lane = t & 31;
    int r0 = warp * 4;

    float acc0[4] = {0.f, 0.f, 0.f, 0.f};
    float acc1[4] = {0.f, 0.f, 0.f, 0.f};

    #pragma unroll
    for (int k = 0; k < K; k++) {
        float w0 = Ws[k * NOUT + lane];
        float w1 = (lane + 32 < NOUT) ? Ws[k * NOUT + lane + 32] : 0.f;
        #pragma unroll
        for (int r = 0; r < 4; r++) {
            float xv = Xs[(r0 + r) * K + k];   // broadcast within warp
            acc0[r] = fmaf(xv, w0, acc0[r]);
            acc1[r] = fmaf(xv, w1, acc1[r]);
        }
    }

    float b0 = B[lane];
    float b1 = (lane + 32 < NOUT) ? B[lane + 32] : 0.f;

    #pragma unroll
    for (int r = 0; r < 4; r++) {
        int gr = row0 + r0 + r;
        if (gr >= n) continue;
        float s = SCALE_OUT ? dis[gr] : 1.f;
        float v0 = (acc0[r] + b0) * s;
        out0[(size_t)gr * NOUT + lane] = v0;
        if (out1) out1[(size_t)gr * NOUT + lane] = v0;
        if (lane + 32 < NOUT) {
            float v1 = (acc1[r] + b1) * s;
            out0[(size_t)gr * NOUT + lane + 32] = v1;
            if (out1) out1[(size_t)gr * NOUT + lane + 32] = v1;
        }
    }
}

// ---------------------------------------------------------------------------
// Edge scatter: acc[dst] += u[src]. 16 threads per edge, float4 per thread,
// vector RED atomics (sm_90+). u/acc working set (51MB) is L2-resident.
// ---------------------------------------------------------------------------
__global__ void edge_kernel(const int* __restrict__ src,
                            const int* __restrict__ dst,
                            const float* __restrict__ u,
                            float* __restrict__ acc,
                            int E) {
    int idx = blockIdx.x * blockDim.x + threadIdx.x;
    int e = idx >> 4;
    if (e >= E) return;
    int lane = idx & 15;
    int s = __ldg(src + e);
    int d = __ldg(dst + e);
    float4 v = __ldg(reinterpret_cast<const float4*>(u) + (size_t)s * 16 + lane);
    atomicAdd(reinterpret_cast<float4*>(acc) + (size_t)d * 16 + lane, v);
}

// ---------------------------------------------------------------------------
extern "C" void kernel_launch(void* const* d_in, const int* in_sizes, int n_in,
                              void* d_out, int out_size) {
    const float* x    = (const float*)d_in[0];
    const int*   ei   = (const int*)d_in[1];
    const float* W0   = (const float*)d_in[2];
    const float* b0   = (const float*)d_in[3];
    const float* W1   = (const float*)d_in[4];
    const float* b1   = (const float*)d_in[5];
    const float* W2   = (const float*)d_in[6];
    const float* b2   = (const float*)d_in[7];
    const float* Wout = (const float*)d_in[8];
    const float* bout = (const float*)d_in[9];
    float* out = (float*)d_out;

    const int N = in_sizes[0] / F_IN;    // 100000
    const int E = in_sizes[1] / 2;       // 1600000
    const int* src = ei;
    const int* dst = ei + E;

    float *uA, *accA, *uB, *accB, *dis;
    int* deg;
    cudaGetSymbolAddress((void**)&uA,   g_uA);
    cudaGetSymbolAddress((void**)&accA, g_accA);
    cudaGetSymbolAddress((void**)&uB,   g_uB);
    cudaGetSymbolAddress((void**)&accB, g_accB);
    cudaGetSymbolAddress((void**)&deg,  g_deg);
    cudaGetSymbolAddress((void**)&dis,  g_dis);

    const int TPB = 256;
    dim3 gemm_grid((N + 31) / 32);
    dim3 edge_grid((E * 16 + TPB - 1) / TPB);

    // 1. Degrees & dis = rsqrt(deg+1)
    cudaMemsetAsync(deg, 0, N * sizeof(int), 0);
    count_deg_kernel<<<(E + TPB - 1) / TPB, TPB>>>(dst, E, deg);
    dis_kernel<<<(N + TPB - 1) / TPB, TPB>>>(deg, dis, N);

    // 2. Layer 0: u = dis*(x@W0+b0); acc = u (self loop); acc[dst] += u[src]
    gemm_kernel<F_IN, HID, false, true><<<gemm_grid, TPB>>>(x, W0, b0, dis, uA, accA, N);
    edge_kernel<<<edge_grid, TPB>>>(src, dst, uA, accA, E);

    // 3. Layer 1: input = relu(dis*accA)
    gemm_kernel<HID, HID, true, true><<<gemm_grid, TPB>>>(accA, W1, b1, dis, uB, accB, N);
    edge_kernel<<<edge_grid, TPB>>>(src, dst, uB, accB, E);

    // 4. Layer 2
    gemm_kernel<HID, HID, true, true><<<gemm_grid, TPB>>>(accB, W2, b2, dis, uA, accA, N);
    edge_kernel<<<edge_grid, TPB>>>(src, dst, uA, accA, E);

    // 5. Output head: relu(dis*accA) @ Wout + bout  (no output scaling)
    gemm_kernel<HID, OUTD, true, false><<<gemm_grid, TPB>>>(accA, Wout, bout, dis, out, nullptr, N);
}

// round 2
// speedup vs baseline: 1.2828x; 1.2828x over previous
#include <cuda_runtime.h>
#include <cuda_bf16.h>
#include <cstdint>

#define NN   100000
#define EE   1600000
#define F_IN 128
#define HID  64
#define OUTD 40

// Scratch (device globals — allocation is forbidden)
__device__ float g_uA[NN * HID];
__device__ float g_accA[NN * HID];
__device__ float g_uB[NN * HID];
__device__ float g_accB[NN * HID];
__device__ int   g_deg[NN];
__device__ float g_dis[NN];
__device__ int   g_rowptr[NN];
__device__ int   g_cursor[NN];
__device__ int   g_colidx[EE];
__device__ int   g_bsum[256];

// ---------------------------------------------------------------------------
// Prep: degree histogram + dis = rsqrt(deg+1)
// ---------------------------------------------------------------------------
__global__ void count_deg_kernel(const int* __restrict__ dst, int E, int* __restrict__ deg) {
    int e = blockIdx.x * blockDim.x + threadIdx.x;
    if (e < E) atomicAdd(&deg[dst[e]], 1);
}

__global__ void dis_kernel(const int* __restrict__ deg, float* __restrict__ dis, int n) {
    int v = blockIdx.x * blockDim.x + threadIdx.x;
    if (v < n) dis[v] = rsqrtf((float)(deg[v] + 1));
}

// ---------------------------------------------------------------------------
// CSR build: exclusive scan of deg (3 kernels) + scatter edges by dst
// ---------------------------------------------------------------------------
__global__ void scan1_kernel(const int* __restrict__ deg, int* __restrict__ rowptr,
                             int* __restrict__ bsum, int n) {
    __shared__ int sh[256];
    int t = threadIdx.x;
    int base = blockIdx.x * 1024 + t * 4;
    int v[4]; int s = 0;
    #pragma unroll
    for (int j = 0; j < 4; j++) {
        v[j] = (base + j < n) ? deg[base + j] : 0;
        s += v[j];
    }
    sh[t] = s;
    // Hillis-Steele inclusive scan over 256 thread sums
    for (int off = 1; off < 256; off <<= 1) {
        __syncthreads();
        int x = (t >= off) ? sh[t - off] : 0;
        __syncthreads();
        sh[t] += x;
    }
    __syncthreads();
    int excl = sh[t] - s;
    int run = 0;
    #pragma unroll
    for (int j = 0; j < 4; j++) {
        if (base + j < n) rowptr[base + j] = excl + run;
        run += v[j];
    }
    if (t == 255) bsum[blockIdx.x] = sh[255];
}

__global__ void scan2_kernel(int* __restrict__ bsum, int nb) {
    // single thread: nb <= 128, trivial
    if (threadIdx.x == 0 && blockIdx.x == 0) {
        int s = 0;
        for (int i = 0; i < nb; i++) { int x = bsum[i]; bsum[i] = s; s += x; }
    }
}

__global__ void scan3_kernel(const int* __restrict__ bsum, int* __restrict__ rowptr,
                             int* __restrict__ cursor, int n) {
    int i = blockIdx.x * blockDim.x + threadIdx.x;
    if (i < n) {
        int r = rowptr[i] + bsum[i >> 10];
        rowptr[i] = r;
        cursor[i] = r;
    }
}

__global__ void scatter_kernel(const int* __restrict__ src, const int* __restrict__ dst,
                               int* __restrict__ cursor, int* __restrict__ colidx, int E) {
    int e = blockIdx.x * blockDim.x + threadIdx.x;
    if (e < E) {
        int p = atomicAdd(&cursor[dst[e]], 1);
        colidx[p] = src[e];
    }
}

// ---------------------------------------------------------------------------
// Fast GEMM for NOUT=64 using packed fma.rn.f32x2.
// Block 256 threads -> 32 rows x 64 cols; thread = 2 rows x 4 cols.
// W pairs come free from LDS.128 (two packed f32x2); X stored duplicated (x,x).
// u = dis[row] * ( [maybe relu(dis*X)] @ W + b )
// ---------------------------------------------------------------------------
template<int K, bool RELU_IN>
__global__ void gemm64_kernel(const float* __restrict__ X,
                              const float* __restrict__ W,
                              const float* __restrict__ B,
                              const float* __restrict__ dis,
                              float* __restrict__ u, int n) {
    constexpr int KC = 64;
    constexpr int XSTR = KC + 1;                 // float2 stride (bank-conflict pad)
    __shared__ float  Ws[KC * 64];               // 16 KB
    __shared__ float2 Xd[32 * XSTR];             // ~16.6 KB, duplicated (x,x)

    int t = threadIdx.x;
    int row0 = blockIdx.x * 32;
    int tix = t & 15;          // col group: cols tix*4 .. tix*4+3
    int tiy = t >> 4;          // row group: rows tiy*2, tiy*2+1

    unsigned long long acc[2][2];
    acc[0][0] = acc[0][1] = acc[1][0] = acc[1][1] = 0ull;  // packed (0.f, 0.f)

    for (int k0 = 0; k0 < K; k0 += KC) {
        // W chunk [KC x 64]
        #pragma unroll
        for (int i = t; i < KC * 64 / 4; i += 256)
            ((float4*)Ws)[i] = ((const float4*)(W + k0 * 64))[i];
        // X chunk [32 x KC], duplicated per element, ReLU+scale fused into read
        #pragma unroll
        for (int i = t; i < 32 * KC / 4; i += 256) {
            int r = i / (KC / 4);
            int c = (i % (KC / 4)) * 4;
            int gr = row0 + r;
            float4 x = {0.f, 0.f, 0.f, 0.f};
            if (gr < n) {
                x = *(const float4*)(X + (size_t)gr * K + k0 + c);
                if (RELU_IN) {
                    float s = dis[gr];
                    x.x = fmaxf(x.x, 0.f) * s; x.y = fmaxf(x.y, 0.f) * s;
                    x.z = fmaxf(x.z, 0.f) * s; x.w = fmaxf(x.w, 0.f) * s;
                }
            }
            float2* p = &Xd[r * XSTR + c];
            p[0] = make_float2(x.x, x.x); p[1] = make_float2(x.y, x.y);
            p[2] = make_float2(x.z, x.z); p[3] = make_float2(x.w, x.w);
        }
        __syncthreads();

        #pragma unroll
        for (int k = 0; k < KC; k++) {
            ulonglong2 w = *reinterpret_cast<const ulonglong2*>(&Ws[k * 64 + tix * 4]);
            unsigned long long x0 = *reinterpret_cast<const unsigned long long*>(&Xd[(tiy * 2 + 0) * XSTR + k]);
            unsigned long long x1 = *reinterpret_cast<const unsigned long long*>(&Xd[(tiy * 2 + 1) * XSTR + k]);
            asm("fma.rn.f32x2 %0, %1, %2, %0;" : "+l"(acc[0][0]) : "l"(x0), "l"(w.x));
            asm("fma.rn.f32x2 %0, %1, %2, %0;" : "+l"(acc[0][1]) : "l"(x0), "l"(w.y));
            asm("fma.rn.f32x2 %0, %1, %2, %0;" : "+l"(acc[1][0]) : "l"(x1), "l"(w.x));
            asm("fma.rn.f32x2 %0, %1, %2, %0;" : "+l"(acc[1][1]) : "l"(x1), "l"(w.y));
        }
        __syncthreads();
    }

    float4 b4 = *(const float4*)(B + tix * 4);
    #pragma unroll
    for (int r = 0; r < 2; r++) {
        int gr = row0 + tiy * 2 + r;
        if (gr >= n) continue;
        float s = dis[gr];
        float4 o;
        o.x = (__uint_as_float((unsigned)(acc[r][0] & 0xffffffffu)) + b4.x) * s;
        o.y = (__uint_as_float((unsigned)(acc[r][0] >> 32))         + b4.y) * s;
        o.z = (__uint_as_float((unsigned)(acc[r][1] & 0xffffffffu)) + b4.z) * s;
        o.w = (__uint_as_float((unsigned)(acc[r][1] >> 32))         + b4.w) * s;
        *(float4*)(u + (size_t)gr * 64 + tix * 4) = o;
    }
}

// ---------------------------------------------------------------------------
// Output head GEMM (NOUT=40): simple warp-per-4-rows kernel
// ---------------------------------------------------------------------------
template<int K, int NOUT>
__global__ void gemm_head_kernel(const float* __restrict__ X,
                                 const float* __restrict__ W,
                                 const float* __restrict__ B,
                                 const float* __restrict__ dis,
                                 float* __restrict__ out, int n) {
    __shared__ float Ws[K * NOUT];
    __shared__ float Xs[32 * K];

    int t = threadIdx.x;
    int row0 = blockIdx.x * 32;

    #pragma unroll 4
    for (int i = t; i < K * NOUT; i += 256) Ws[i] = W[i];
    #pragma unroll 4
    for (int i = t; i < 32 * K; i += 256) {
        int r = i / K, k = i - r * K;
        int gr = row0 + r;
        float v = 0.f;
        if (gr < n) v = fmaxf(X[(size_t)gr * K + k], 0.f) * dis[gr];
        Xs[i] = v;
    }
    __syncthreads();

    int warp = t >> 5, lane = t & 31;
    int r0 = warp * 4;
    float acc0[4] = {0.f, 0.f, 0.f, 0.f};
    float acc1[4] = {0.f, 0.f, 0.f, 0.f};

    #pragma unroll
    for (int k = 0; k < K; k++) {
        float w0 = Ws[k * NOUT + lane];
        float w1 = (lane + 32 < NOUT) ? Ws[k * NOUT + lane + 32] : 0.f;
        #pragma unroll
        for (int r = 0; r < 4; r++) {
            float xv = Xs[(r0 + r) * K + k];
            acc0[r] = fmaf(xv, w0, acc0[r]);
            acc1[r] = fmaf(xv, w1, acc1[r]);
        }
    }

    float b0 = B[lane];
    float b1 = (lane + 32 < NOUT) ? B[lane + 32] : 0.f;
    #pragma unroll
    for (int r = 0; r < 4; r++) {
        int gr = row0 + r0 + r;
        if (gr >= n) continue;
        out[(size_t)gr * NOUT + lane] = acc0[r] + b0;
        if (lane + 32 < NOUT) out[(size_t)gr * NOUT + lane + 32] = acc1[r] + b1;
    }
}

// ---------------------------------------------------------------------------
// Pull aggregation: acc[v] = u[v] + sum_{s in in-nbrs(v)} u[s]
// Half-warp (16 lanes) per node, float4 per lane, unroll-2 for MLP.
// ---------------------------------------------------------------------------
__global__ void pull_kernel(const int* __restrict__ rowptr,
                            const int* __restrict__ deg,
                            const int* __restrict__ colidx,
                            const float* __restrict__ u,
                            float* __restrict__ acc, int n) {
    int idx = blockIdx.x * blockDim.x + threadIdx.x;
    int v = idx >> 4;
    if (v >= n) return;
    int h = idx & 15;

    const float4* uv = (const float4*)u;
    float4 a = __ldg(uv + (size_t)v * 16 + h);   // self loop
    int s0 = rowptr[v];
    int d = deg[v];

    int j = 0;
    for (; j + 2 <= d; j += 2) {
        int c0 = __ldg(colidx + s0 + j);
        int c1 = __ldg(colidx + s0 + j + 1);
        float4 x0 = __ldg(uv + (size_t)c0 * 16 + h);
        float4 x1 = __ldg(uv + (size_t)c1 * 16 + h);
        a.x += x0.x; a.y += x0.y; a.z += x0.z; a.w += x0.w;
        a.x += x1.x; a.y += x1.y; a.z += x1.z; a.w += x1.w;
    }
    if (j < d) {
        int c0 = __ldg(colidx + s0 + j);
        float4 x0 = __ldg(uv + (size_t)c0 * 16 + h);
        a.x += x0.x; a.y += x0.y; a.z += x0.z; a.w += x0.w;
    }
    ((float4*)acc)[(size_t)v * 16 + h] = a;
}

// ---------------------------------------------------------------------------
extern "C" void kernel_launch(void* const* d_in, const int* in_sizes, int n_in,
                              void* d_out, int out_size) {
    const float* x    = (const float*)d_in[0];
    const int*   ei   = (const int*)d_in[1];
    const float* W0   = (const float*)d_in[2];
    const float* b0   = (const float*)d_in[3];
    const float* W1   = (const float*)d_in[4];
    const float* b1   = (const float*)d_in[5];
    const float* W2   = (const float*)d_in[6];
    const float* b2   = (const float*)d_in[7];
    const float* Wout = (const float*)d_in[8];
    const float* bout = (const float*)d_in[9];
    float* out = (float*)d_out;

    const int N = in_sizes[0] / F_IN;
    const int E = in_sizes[1] / 2;
    const int* src = ei;
    const int* dst = ei + E;

    float *uA, *accA, *uB, *accB, *dis;
    int *deg, *rowptr, *cursor, *colidx, *bsum;
    cudaGetSymbolAddress((void**)&uA,     g_uA);
    cudaGetSymbolAddress((void**)&accA,   g_accA);
    cudaGetSymbolAddress((void**)&uB,     g_uB);
    cudaGetSymbolAddress((void**)&accB,   g_accB);
    cudaGetSymbolAddress((void**)&deg,    g_deg);
    cudaGetSymbolAddress((void**)&dis,    g_dis);
    cudaGetSymbolAddress((void**)&rowptr, g_rowptr);
    cudaGetSymbolAddress((void**)&cursor, g_cursor);
    cudaGetSymbolAddress((void**)&colidx, g_colidx);
    cudaGetSymbolAddress((void**)&bsum,   g_bsum);

    const int TPB = 256;
    dim3 g64_grid((N + 31) / 32);
    dim3 pull_grid(((size_t)N * 16 + TPB - 1) / TPB);
    int nscan = (N + 1023) / 1024;

    // Prep: degrees, dis
    cudaMemsetAsync(deg, 0, N * sizeof(int), 0);
    count_deg_kernel<<<(E + TPB - 1) / TPB, TPB>>>(dst, E, deg);
    dis_kernel<<<(N + TPB - 1) / TPB, TPB>>>(deg, dis, N);

    // CSR build (dst-grouped)
    scan1_kernel<<<nscan, 256>>>(deg, rowptr, bsum, N);
    scan2_kernel<<<1, 32>>>(bsum, nscan);
    scan3_kernel<<<(N + TPB - 1) / TPB, TPB>>>(bsum, rowptr, cursor, N);
    scatter_kernel<<<(E + TPB - 1) / TPB, TPB>>>(src, dst, cursor, colidx, E);

    // Layer 0
    gemm64_kernel<F_IN, false><<<g64_grid, TPB>>>(x, W0, b0, dis, uA, N);
    pull_kernel<<<pull_grid, TPB>>>(rowptr, deg, colidx, uA, accA, N);
    // Layer 1
    gemm64_kernel<HID, true><<<g64_grid, TPB>>>(accA, W1, b1, dis, uB, N);
    pull_kernel<<<pull_grid, TPB>>>(rowptr, deg, colidx, uB, accB, N);
    // Layer 2
    gemm64_kernel<HID, true><<<g64_grid, TPB>>>(accB, W2, b2, dis, uA, N);
    pull_kernel<<<pull_grid, TPB>>>(rowptr, deg, colidx, uA, accA, N);
    // Head
    gemm_head_kernel<HID, OUTD><<<g64_grid, TPB>>>(accA, Wout, bout, dis, out, N);
}